// round 12
// baseline (speedup 1.0000x reference)
#include <cuda_runtime.h>
#include <cstdint>
#include <cstddef>

#define DIM      128
#define ROWS     64          // rows per block
#define THREADS  256
#define RPW      8           // rows per warp
#define XPITCH   68          // padded pitch (floats) of transposed x tile
#define KSEL     32
#define VCHUNK   16          // d-rows of v staged per pass (8 passes)

// smem: dup'd v chunk [16][1024B] = 16KB, then x^T [128][68] fp32.
// stage (8 warps x 4 rows x 32 x uint2 = 8KB) overlays the v region
// during selection (v is dead by then).
#define VBYTES     (VCHUNK*1024)
#define SMEM_BYTES (VBYTES + DIM*XPITCH*4)

__device__ float g_inv_len;

// ---------------------------------------------------------------------------
// helpers
// ---------------------------------------------------------------------------
__device__ __forceinline__ void fma2(unsigned long long& c,
                                     unsigned long long a,
                                     unsigned long long b) {
    asm("fma.rn.f32x2 %0, %1, %2, %0;" : "+l"(c) : "l"(a), "l"(b));
}
// order-preserving float -> u32 key (larger float => larger key)
__device__ __forceinline__ unsigned fkey(float f) {
    unsigned u = __float_as_uint(f);
    return (u & 0x80000000u) ? ~u : (u | 0x80000000u);
}
__device__ __forceinline__ float unfkey(unsigned m) {
    unsigned u = (m & 0x80000000u) ? (m & 0x7fffffffu) : ~m;
    return __uint_as_float(u);
}

union F2U { unsigned long long u; float2 f; };

// stable desc comparator: larger key first; equal keys -> lower col first
#define CSWAP(ka, ca, kb, cb)                                   \
    {                                                           \
        bool sw = (ka < kb) || (ka == kb && ca > cb);           \
        unsigned tk = sw ? kb : ka;                             \
        unsigned tc = sw ? cb : ca;                             \
        kb = sw ? ka : kb;  cb = sw ? ca : cb;                  \
        ka = tk;            ca = tc;                            \
    }

// ---------------------------------------------------------------------------
// 1/||v||_F  (one block)
// ---------------------------------------------------------------------------
__global__ void norm_kernel(const float* __restrict__ v) {
    __shared__ float red[8];
    float s = 0.f;
    for (int i = threadIdx.x; i < DIM * DIM; i += blockDim.x) {
        float a = v[i];
        s = fmaf(a, a, s);
    }
    #pragma unroll
    for (int o = 16; o; o >>= 1) s += __shfl_xor_sync(0xffffffffu, s, o);
    if ((threadIdx.x & 31) == 0) red[threadIdx.x >> 5] = s;
    __syncthreads();
    if (threadIdx.x == 0) {
        float t = 0.f;
        #pragma unroll
        for (int i = 0; i < 8; i++) t += red[i];
        g_inv_len = 1.0f / sqrtf(t);
    }
}

// ---------------------------------------------------------------------------
// fused  y = x@v ; top-32 per row ; out = x[idx] * sigmoid(y[idx]/||v||)
// ---------------------------------------------------------------------------
__global__ __launch_bounds__(THREADS, 4)
void pool_kernel(const float* __restrict__ x, const float* __restrict__ v,
                 float* __restrict__ out, int nrows) {
    extern __shared__ float smem[];
    char*  v_sh  = (char*)smem;                   // dup'd v chunk, 16KB
    float* x_sh  = smem + VBYTES / 4;             // x^T: [d][row], pitch 68
    uint2* stage = (uint2*)smem;                  // overlays v post-GEMM

    const int tid  = threadIdx.x;
    const int row0 = blockIdx.x * ROWS;
    const int warp = tid >> 5, lane = tid & 31;
    const int r0 = warp * RPW;

    // ---- load x tile transposed (one-off) ----
    for (int e = tid; e < ROWS * DIM; e += THREADS) {
        int r = e >> 7, d = e & 127;
        float val = (row0 + r < nrows) ? x[(size_t)(row0 + r) * DIM + d] : 0.f;
        x_sh[d * XPITCH + r] = val;
    }

    // lane l owns columns (31-l)*4 .. (31-l)*4+3  (so FLO(ballot) = lowest col)
    const int col0 = (31 - lane) * 4;
    const int voff1 = col0 * 4;          // byte offset of dup(col0), dup(col0+1)
    const int voff2 = 512 + col0 * 4;    // byte offset of dup(col0+2), dup(col0+3)

    unsigned long long acc[4][4];
    #pragma unroll
    for (int a = 0; a < 4; a++)
        #pragma unroll
        for (int b = 0; b < 4; b++) acc[a][b] = 0ull;

    // ---- GEMM in eight d-passes (v staged dup'd, 16 rows at a time) ----
    #pragma unroll 1
    for (int pass = 0; pass < 8; ++pass) {
        __syncthreads();   // pass0: pairs with x load; later: v_sh reuse fence
        {
            const float4* vg = (const float4*)(v + pass * VCHUNK * DIM);
            for (int i = tid; i < VCHUNK * DIM / 4; i += THREADS) {
                float4 a = vg[i];
                int vrow = i >> 5, j = i & 31;
                char* base = v_sh + vrow * 1024 + j * 16;
                *(float4*)(base)       = make_float4(a.x, a.x, a.y, a.y);
                *(float4*)(base + 512) = make_float4(a.z, a.z, a.w, a.w);
            }
        }
        __syncthreads();

        const float* xbase = x_sh + pass * VCHUNK * XPITCH + r0;

        #pragma unroll 8
        for (int dd = 0; dd < VCHUNK; ++dd) {
            const char* vr = v_sh + dd * 1024;
            ulonglong2 vA = *(const ulonglong2*)(vr + voff1);  // dup c0 | dup c1
            ulonglong2 vB = *(const ulonglong2*)(vr + voff2);  // dup c2 | dup c3
            const float* xr = xbase + dd * XPITCH;
            ulonglong2 xa = *(const ulonglong2*)(xr + 0);      // rows01 | rows23
            ulonglong2 xb = *(const ulonglong2*)(xr + 4);      // rows45 | rows67
            fma2(acc[0][0], xa.x, vA.x); fma2(acc[0][1], xa.x, vA.y);
            fma2(acc[0][2], xa.x, vB.x); fma2(acc[0][3], xa.x, vB.y);
            fma2(acc[1][0], xa.y, vA.x); fma2(acc[1][1], xa.y, vA.y);
            fma2(acc[1][2], xa.y, vB.x); fma2(acc[1][3], xa.y, vB.y);
            fma2(acc[2][0], xb.x, vA.x); fma2(acc[2][1], xb.x, vA.y);
            fma2(acc[2][2], xb.x, vB.x); fma2(acc[2][3], xb.x, vB.y);
            fma2(acc[3][0], xb.y, vA.x); fma2(acc[3][1], xb.y, vA.y);
            fma2(acc[3][2], xb.y, vB.x); fma2(acc[3][3], xb.y, vB.y);
        }
    }
    __syncthreads();       // v region dead -> becomes stage buffers

    const float inv_len = g_inv_len;
    uint2* st = stage + warp * 4 * KSEL;   // 4 row-buffers of 32 uint2 per warp

    // ---- top-32 per row: branch-free, FOUR rows interleaved per loop ----
    #pragma unroll 1
    for (int grp = 0; grp < 2; ++grp) {
        unsigned kk[4][4], cc[4][4];
        // rows r0+4*grp+{0,1,2,3} = acc[2g].lo, acc[2g].hi, acc[2g+1].lo, acc[2g+1].hi
        #pragma unroll
        for (int h = 0; h < 2; ++h) {
            F2U t0, t1, t2, t3;
            t0.u = acc[2 * grp + h][0]; t1.u = acc[2 * grp + h][1];
            t2.u = acc[2 * grp + h][2]; t3.u = acc[2 * grp + h][3];
            int jA = 2 * h, jB = 2 * h + 1;
            kk[jA][0] = fkey(t0.f.x); kk[jA][1] = fkey(t1.f.x);
            kk[jA][2] = fkey(t2.f.x); kk[jA][3] = fkey(t3.f.x);
            kk[jB][0] = fkey(t0.f.y); kk[jB][1] = fkey(t1.f.y);
            kk[jB][2] = fkey(t2.f.y); kk[jB][3] = fkey(t3.f.y);
        }
        // NOTE: mapping above gives row order: 4g+0 (acc[2g].x), 4g+1? careful:
        // jA=0 is acc[2g] low = row 4g+0; jB=1 is acc[2g] high = row 4g+1;
        // h=1: jA=2 acc[2g+1] low = row 4g+2; jB=3 high = row 4g+3.  OK.
        #pragma unroll
        for (int j = 0; j < 4; ++j) {
            cc[j][0] = col0 + 0; cc[j][1] = col0 + 1;
            cc[j][2] = col0 + 2; cc[j][3] = col0 + 3;
            CSWAP(kk[j][0], cc[j][0], kk[j][1], cc[j][1]);
            CSWAP(kk[j][2], cc[j][2], kk[j][3], cc[j][3]);
            CSWAP(kk[j][0], cc[j][0], kk[j][2], cc[j][2]);
            CSWAP(kk[j][1], cc[j][1], kk[j][3], cc[j][3]);
            CSWAP(kk[j][1], cc[j][1], kk[j][2], cc[j][2]);
        }

        #pragma unroll 2
        for (int i = 0; i < KSEL; ++i) {
            #pragma unroll
            for (int j = 0; j < 4; ++j) {
                unsigned m   = __reduce_max_sync(0xffffffffu, kk[j][0]);
                unsigned bal = __ballot_sync(0xffffffffu, kk[j][0] == m);
                bool win = (lane == 31 - __clz(bal));   // FLO -> lowest column
                if (win) st[j * KSEL + i] = make_uint2(cc[j][0], kk[j][0]);
                kk[j][0] = win ? kk[j][1] : kk[j][0];  cc[j][0] = win ? cc[j][1] : cc[j][0];
                kk[j][1] = win ? kk[j][2] : kk[j][1];  cc[j][1] = win ? cc[j][2] : cc[j][1];
                kk[j][2] = win ? kk[j][3] : kk[j][2];  cc[j][2] = win ? cc[j][3] : cc[j][2];
                kk[j][3] = win ? 0u       : kk[j][3];
            }
        }
        __syncwarp();

        // ---- epilogue: gather x from SMEM, sigmoid, store ----
        #pragma unroll
        for (int j = 0; j < 4; ++j) {
            const int rowl = r0 + 4 * grp + j;
            const int grow = row0 + rowl;
            if (grow < nrows) {
                uint2 p = st[j * KSEL + lane];
                float d  = unfkey(p.y) * inv_len;
                float sg = 1.0f / (1.0f + __expf(-d));
                float xv = x_sh[p.x * XPITCH + rowl];
                out[(size_t)grow * KSEL + lane] = xv * sg;
            }
        }
        __syncwarp();
    }
}

// ---------------------------------------------------------------------------
extern "C" void kernel_launch(void* const* d_in, const int* in_sizes, int n_in,
                              void* d_out, int out_size) {
    const float* x = (const float*)d_in[0];
    const float* v = (const float*)d_in[1];
    float* out = (float*)d_out;
    const int nrows = in_sizes[0] / DIM;

    cudaFuncSetAttribute(pool_kernel,
                         cudaFuncAttributeMaxDynamicSharedMemorySize, SMEM_BYTES);

    norm_kernel<<<1, 256>>>(v);
    const int grid = (nrows + ROWS - 1) / ROWS;
    pool_kernel<<<grid, THREADS, SMEM_BYTES>>>(x, v, out, nrows);
}

// round 13
// speedup vs baseline: 1.0914x; 1.0914x over previous
#include <cuda_runtime.h>
#include <cstdint>
#include <cstddef>

#define DIM      128
#define ROWS     64          // rows per block
#define THREADS  256
#define RPW      8           // rows per warp
#define XPITCH   68          // padded pitch (floats) of transposed x tile
#define KSEL     32
#define VCHUNK   32          // d-rows of v staged per pass (4 passes)

// smem: v chunk [32][128] fp32 (16KB) + x^T [128][68] fp32 (34.8KB).
// stage (8 warps x 4 rows x 32 x uint2 = 8KB) overlays the v region during
// selection (v dead by then).  51.2KB/CTA -> 4 CTAs/SM.
#define VBYTES     (VCHUNK*DIM*4)
#define SMEM_BYTES (VBYTES + DIM*XPITCH*4)

__device__ float g_inv_len;

// ---------------------------------------------------------------------------
// helpers
// ---------------------------------------------------------------------------
__device__ __forceinline__ unsigned long long dup_f32(float a) {
    unsigned long long r; unsigned u = __float_as_uint(a);
    asm("mov.b64 %0, {%1, %1};" : "=l"(r) : "r"(u));
    return r;
}
__device__ __forceinline__ void fma2(unsigned long long& c,
                                     unsigned long long a,
                                     unsigned long long b) {
    asm("fma.rn.f32x2 %0, %1, %2, %0;" : "+l"(c) : "l"(a), "l"(b));
}
// order-preserving float -> u32 key (larger float => larger key)
__device__ __forceinline__ unsigned fkey(float f) {
    unsigned u = __float_as_uint(f);
    return (u & 0x80000000u) ? ~u : (u | 0x80000000u);
}
__device__ __forceinline__ float unfkey(unsigned m) {
    unsigned u = (m & 0x80000000u) ? (m & 0x7fffffffu) : ~m;
    return __uint_as_float(u);
}

union F2U { unsigned long long u; float2 f; };

// stable desc comparator: larger key first; equal keys -> lower col first
#define CSWAP(ka, ca, kb, cb)                                   \
    {                                                           \
        bool sw = (ka < kb) || (ka == kb && ca > cb);           \
        unsigned tk = sw ? kb : ka;                             \
        unsigned tc = sw ? cb : ca;                             \
        kb = sw ? ka : kb;  cb = sw ? ca : cb;                  \
        ka = tk;            ca = tc;                            \
    }

// ---------------------------------------------------------------------------
// 1/||v||_F  (one block)
// ---------------------------------------------------------------------------
__global__ void norm_kernel(const float* __restrict__ v) {
    __shared__ float red[8];
    float s = 0.f;
    for (int i = threadIdx.x; i < DIM * DIM; i += blockDim.x) {
        float a = v[i];
        s = fmaf(a, a, s);
    }
    #pragma unroll
    for (int o = 16; o; o >>= 1) s += __shfl_xor_sync(0xffffffffu, s, o);
    if ((threadIdx.x & 31) == 0) red[threadIdx.x >> 5] = s;
    __syncthreads();
    if (threadIdx.x == 0) {
        float t = 0.f;
        #pragma unroll
        for (int i = 0; i < 8; i++) t += red[i];
        g_inv_len = 1.0f / sqrtf(t);
    }
}

// ---------------------------------------------------------------------------
// fused  y = x@v ; top-32 per row ; out = x[idx] * sigmoid(y[idx]/||v||)
// ---------------------------------------------------------------------------
__global__ __launch_bounds__(THREADS, 4)
void pool_kernel(const float* __restrict__ x, const float* __restrict__ v,
                 float* __restrict__ out, int nrows) {
    extern __shared__ float smem[];
    float* v_sh  = smem;                          // [32][128], per pass
    float* x_sh  = smem + VBYTES / 4;             // x^T: [d][row], pitch 68
    uint2* stage = (uint2*)smem;                  // overlays v post-GEMM

    const int tid  = threadIdx.x;
    const int row0 = blockIdx.x * ROWS;
    const int warp = tid >> 5, lane = tid & 31;
    const int r0 = warp * RPW;

    // ---- load x tile transposed (one-off) ----
    for (int e = tid; e < ROWS * DIM; e += THREADS) {
        int r = e >> 7, d = e & 127;
        float val = (row0 + r < nrows) ? x[(size_t)(row0 + r) * DIM + d] : 0.f;
        x_sh[d * XPITCH + r] = val;
    }

    // lane l owns columns (31-l)*4 .. (31-l)*4+3  (so FLO(ballot) = lowest col)
    const int col0 = (31 - lane) * 4;

    unsigned long long acc[4][4];
    #pragma unroll
    for (int a = 0; a < 4; a++)
        #pragma unroll
        for (int b = 0; b < 4; b++) acc[a][b] = 0ull;

    // ---- GEMM in four d-passes (v staged 32 rows at a time) ----
    #pragma unroll 1
    for (int pass = 0; pass < 4; ++pass) {
        __syncthreads();   // pass0: pairs with x load; later: v_sh reuse fence
        {
            const float4* vg = (const float4*)(v + pass * VCHUNK * DIM);
            float4*       vs = (float4*)v_sh;
            for (int i = tid; i < VCHUNK * DIM / 4; i += THREADS) vs[i] = vg[i];
        }
        __syncthreads();

        const float* vcol  = v_sh + col0;
        const float* xbase = x_sh + pass * VCHUNK * XPITCH + r0;

        #pragma unroll 8
        for (int dd = 0; dd < VCHUNK; ++dd) {
            float4 vv = *(const float4*)(vcol + (size_t)dd * DIM);
            const float* xr = xbase + dd * XPITCH;
            ulonglong2 xa = *(const ulonglong2*)(xr + 0);   // rows01 | rows23
            ulonglong2 xb = *(const ulonglong2*)(xr + 4);   // rows45 | rows67
            unsigned long long v0 = dup_f32(vv.x), v1 = dup_f32(vv.y);
            unsigned long long v2 = dup_f32(vv.z), v3 = dup_f32(vv.w);
            fma2(acc[0][0], xa.x, v0); fma2(acc[0][1], xa.x, v1);
            fma2(acc[0][2], xa.x, v2); fma2(acc[0][3], xa.x, v3);
            fma2(acc[1][0], xa.y, v0); fma2(acc[1][1], xa.y, v1);
            fma2(acc[1][2], xa.y, v2); fma2(acc[1][3], xa.y, v3);
            fma2(acc[2][0], xb.x, v0); fma2(acc[2][1], xb.x, v1);
            fma2(acc[2][2], xb.x, v2); fma2(acc[2][3], xb.x, v3);
            fma2(acc[3][0], xb.y, v0); fma2(acc[3][1], xb.y, v1);
            fma2(acc[3][2], xb.y, v2); fma2(acc[3][3], xb.y, v3);
        }
    }
    __syncthreads();       // v region dead -> becomes stage buffers

    const float inv_len = g_inv_len;
    uint2* st = stage + warp * 4 * KSEL;   // 4 row-buffers of 32 uint2 per warp

    // ---- top-32 per row: branch-free, FOUR rows interleaved per loop ----
    #pragma unroll 1
    for (int grp = 0; grp < 2; ++grp) {
        unsigned kk[4][4], cc[4][4];
        // rows r0+4*grp+{0,1,2,3} = acc[2grp].lo/.hi, acc[2grp+1].lo/.hi
        #pragma unroll
        for (int h = 0; h < 2; ++h) {
            F2U t0, t1, t2, t3;
            t0.u = acc[2 * grp + h][0]; t1.u = acc[2 * grp + h][1];
            t2.u = acc[2 * grp + h][2]; t3.u = acc[2 * grp + h][3];
            int jA = 2 * h, jB = 2 * h + 1;
            kk[jA][0] = fkey(t0.f.x); kk[jA][1] = fkey(t1.f.x);
            kk[jA][2] = fkey(t2.f.x); kk[jA][3] = fkey(t3.f.x);
            kk[jB][0] = fkey(t0.f.y); kk[jB][1] = fkey(t1.f.y);
            kk[jB][2] = fkey(t2.f.y); kk[jB][3] = fkey(t3.f.y);
        }
        #pragma unroll
        for (int j = 0; j < 4; ++j) {
            cc[j][0] = col0 + 0; cc[j][1] = col0 + 1;
            cc[j][2] = col0 + 2; cc[j][3] = col0 + 3;
            CSWAP(kk[j][0], cc[j][0], kk[j][1], cc[j][1]);
            CSWAP(kk[j][2], cc[j][2], kk[j][3], cc[j][3]);
            CSWAP(kk[j][0], cc[j][0], kk[j][2], cc[j][2]);
            CSWAP(kk[j][1], cc[j][1], kk[j][3], cc[j][3]);
            CSWAP(kk[j][1], cc[j][1], kk[j][2], cc[j][2]);
        }

        #pragma unroll 2
        for (int i = 0; i < KSEL; ++i) {
            #pragma unroll
            for (int j = 0; j < 4; ++j) {
                unsigned m   = __reduce_max_sync(0xffffffffu, kk[j][0]);
                unsigned bal = __ballot_sync(0xffffffffu, kk[j][0] == m);
                bool win = (lane == 31 - __clz(bal));   // FLO -> lowest column
                if (win) st[j * KSEL + i] = make_uint2(cc[j][0], kk[j][0]);
                kk[j][0] = win ? kk[j][1] : kk[j][0];  cc[j][0] = win ? cc[j][1] : cc[j][0];
                kk[j][1] = win ? kk[j][2] : kk[j][1];  cc[j][1] = win ? cc[j][2] : cc[j][1];
                kk[j][2] = win ? kk[j][3] : kk[j][2];  cc[j][2] = win ? cc[j][3] : cc[j][2];
                kk[j][3] = win ? 0u       : kk[j][3];
            }
        }
        __syncwarp();

        // ---- epilogue: gather x from SMEM, sigmoid, store ----
        #pragma unroll
        for (int j = 0; j < 4; ++j) {
            const int rowl = r0 + 4 * grp + j;
            const int grow = row0 + rowl;
            if (grow < nrows) {
                uint2 p = st[j * KSEL + lane];
                float d  = unfkey(p.y) * inv_len;
                float sg = 1.0f / (1.0f + __expf(-d));
                float xv = x_sh[p.x * XPITCH + rowl];
                out[(size_t)grow * KSEL + lane] = xv * sg;
            }
        }
        __syncwarp();
    }
}

// ---------------------------------------------------------------------------
extern "C" void kernel_launch(void* const* d_in, const int* in_sizes, int n_in,
                              void* d_out, int out_size) {
    const float* x = (const float*)d_in[0];
    const float* v = (const float*)d_in[1];
    float* out = (float*)d_out;
    const int nrows = in_sizes[0] / DIM;

    cudaFuncSetAttribute(pool_kernel,
                         cudaFuncAttributeMaxDynamicSharedMemorySize, SMEM_BYTES);

    norm_kernel<<<1, 256>>>(v);
    const int grid = (nrows + ROWS - 1) / ROWS;
    pool_kernel<<<grid, THREADS, SMEM_BYTES>>>(x, v, out, nrows);
}

// round 14
// speedup vs baseline: 1.1617x; 1.0644x over previous
#include <cuda_runtime.h>
#include <cuda_fp16.h>
#include <cstdint>
#include <cstddef>

#define DIM       128
#define ROWS_CTA  128
#define THREADS   256
#define RPW       16                    // rows per warp
#define KSEL      32
#define APITCH    136                   // fp16 elems per B row (272 B)
#define BIMG      (DIM*APITCH*2)        // 34816 B per v split image
#define B_OFF     0
#define YPITCH    132                   // fp32 y pitch
#define YCHUNK    (8*YPITCH*4)          // 4224 B per-warp y chunk (8 rows)
#define Y_OFF     (2*BIMG)              // 69632
#define ST_OFF    (Y_OFF + 8*YCHUNK)    // 103424
#define CAND_OFF  (ST_OFF + 8*4*KSEL*8) // 111616
#define SMEM_TOTAL (CAND_OFF + 8*64*4)  // 113664  -> 2 CTAs/SM
#define TAU       1e-4f                 // ~25 sigma of fp16 2-split error

__device__ float g_inv_len;
__device__ __align__(16) unsigned char g_vimg[2][BIMG];

// ---------------------------------------------------------------------------
__device__ __forceinline__ uint32_t smem_u32(const void* p) {
    uint32_t a;
    asm("{ .reg .u64 t; cvta.to.shared.u64 t, %1; cvt.u32.u64 %0, t; }"
        : "=r"(a) : "l"(p));
    return a;
}
__device__ __forceinline__ unsigned fkey(float f) {
    unsigned u = __float_as_uint(f);
    return (u & 0x80000000u) ? ~u : (u | 0x80000000u);
}
__device__ __forceinline__ float unfkey(unsigned m) {
    unsigned u = (m & 0x80000000u) ? (m & 0x7fffffffu) : ~m;
    return __uint_as_float(u);
}
#define CSWAP(ka, ca, kb, cb)                                   \
    {                                                           \
        bool sw = (ka < kb) || (ka == kb && ca > cb);           \
        unsigned tk_ = sw ? kb : ka;                            \
        unsigned tc_ = sw ? cb : ca;                            \
        kb = sw ? ka : kb;  cb = sw ? ca : cb;                  \
        ka = tk_;           ca = tc_;                           \
    }

__device__ __forceinline__ void ldm_x4(uint32_t addr, uint32_t* r) {
    asm volatile("ldmatrix.sync.aligned.m8n8.x4.shared.b16 {%0,%1,%2,%3}, [%4];"
                 : "=r"(r[0]), "=r"(r[1]), "=r"(r[2]), "=r"(r[3]) : "r"(addr));
}
__device__ __forceinline__ void mma_f16(float* c, const uint32_t* a,
                                        uint32_t b0, uint32_t b1) {
    asm volatile(
        "mma.sync.aligned.m16n8k16.row.col.f32.f16.f16.f32 "
        "{%0,%1,%2,%3}, {%4,%5,%6,%7}, {%8,%9}, {%0,%1,%2,%3};"
        : "+f"(c[0]), "+f"(c[1]), "+f"(c[2]), "+f"(c[3])
        : "r"(a[0]), "r"(a[1]), "r"(a[2]), "r"(a[3]), "r"(b0), "r"(b1));
}
// fp16 2-split of a float pair: h0 = rn(v), h1 = rn(v - f32(h0)); (lo=x, hi=y)
__device__ __forceinline__ void split_pair(float2 v, uint32_t& h0, uint32_t& h1) {
    asm("cvt.rn.f16x2.f32 %0, %1, %2;" : "=r"(h0) : "f"(v.y), "f"(v.x));
    float bx, by;
    asm("{\n\t.reg .b16 l, h;\n\tmov.b32 {l, h}, %2;\n\t"
        "cvt.f32.f16 %0, l;\n\tcvt.f32.f16 %1, h;\n\t}"
        : "=f"(bx), "=f"(by) : "r"(h0));
    asm("cvt.rn.f16x2.f32 %0, %1, %2;" : "=r"(h1) : "f"(v.y - by), "f"(v.x - bx));
}

// ---------------------------------------------------------------------------
// prep: 1/||v|| and fp16 2-split images of B[n][k] = v[k][n]
// ---------------------------------------------------------------------------
__global__ void prep_kernel(const float* __restrict__ v) {
    __shared__ float red[8];
    const int tid = threadIdx.x;
    float s = 0.f;
    for (int i = tid; i < DIM * DIM; i += 256) { float a = v[i]; s = fmaf(a, a, s); }
    #pragma unroll
    for (int o = 16; o; o >>= 1) s += __shfl_xor_sync(0xffffffffu, s, o);
    if ((tid & 31) == 0) red[tid >> 5] = s;
    __syncthreads();
    if (tid == 0) {
        float t = 0.f;
        #pragma unroll
        for (int i = 0; i < 8; i++) t += red[i];
        g_inv_len = 1.0f / sqrtf(t);
    }
    for (int i = tid; i < DIM * DIM; i += 256) {
        int k = i >> 7, n = i & 127;
        float a = v[i];
        __half h0 = __float2half_rn(a);
        float r1 = a - __half2float(h0);
        uint32_t off = (uint32_t)(n * APITCH + k) * 2;
        *(__half*)(g_vimg[0] + off) = h0;
        *(__half*)(g_vimg[1] + off) = __float2half_rn(r1);
    }
}

// ---------------------------------------------------------------------------
// rare-path fixup: exact (ascending-k fp32 fma) re-rank of ambiguous rows
// ---------------------------------------------------------------------------
__device__ __noinline__ void fixup_row(const float* __restrict__ x,
                                       const float* __restrict__ vfp,
                                       int grow, const float* __restrict__ ysh_row,
                                       uint2* st_row, int* candbuf, float y31) {
    const int lane = threadIdx.x & 31;
    const int col0 = (31 - lane) * 4;
    const float yt = y31 - TAU;

    int base = 0;
    #pragma unroll
    for (int q = 0; q < 4; ++q) {
        int c = col0 + q;
        bool sel = (ysh_row[c] >= yt);
        unsigned bal = __ballot_sync(0xffffffffu, sel);
        int pos = base + __popc(bal & ((1u << lane) - 1u));
        if (sel && pos < 64) candbuf[pos] = c;
        base += __popc(bal);
    }
    int ncand = base < 64 ? base : 64;
    __syncwarp();

    int c1 = (lane < ncand) ? candbuf[lane] : -1;
    int c2 = (lane + 32 < ncand) ? candbuf[lane + 32] : -1;
    const float* xr = x + (size_t)grow * DIM;
    const float* v1 = vfp + ((c1 >= 0) ? c1 : 0);
    const float* v2 = vfp + ((c2 >= 0) ? c2 : 0);
    float a1 = 0.f, a2 = 0.f;
    #pragma unroll 4
    for (int k = 0; k < DIM; ++k) {
        float xv = __ldg(xr + k);
        a1 = fmaf(xv, __ldg(v1 + (size_t)k * DIM), a1);
        a2 = fmaf(xv, __ldg(v2 + (size_t)k * DIM), a2);
    }

    unsigned hk = (c1 >= 0) ? fkey(a1) : 0u;
    unsigned hc = (c1 >= 0) ? (unsigned)c1 : 0x7fffffffu;
    unsigned tk = (c2 >= 0) ? fkey(a2) : 0u;
    unsigned tc = (c2 >= 0) ? (unsigned)c2 : 0x7fffffffu;
    CSWAP(hk, hc, tk, tc);

    #pragma unroll 1
    for (int i = 0; i < KSEL; ++i) {
        unsigned m = __reduce_max_sync(0xffffffffu, hk);
        bool sel = (hk == m);
        unsigned colx = sel ? hc : 0x7fffffffu;
        unsigned minc = __reduce_min_sync(0xffffffffu, colx);   // jax tie-break
        bool win = sel && (hc == minc);
        if (win) st_row[i] = make_uint2(hc, hk);
        hk = win ? tk : hk;  hc = win ? tc : hc;  tk = win ? 0u : tk;
    }
    __syncwarp();
}

// ---------------------------------------------------------------------------
// main: warp-autonomous fp16 2-split HMMA (3 products) -> y -> top-32 -> out
// ---------------------------------------------------------------------------
__global__ __launch_bounds__(THREADS, 2)
void pool_kernel(const float* __restrict__ x, const float* __restrict__ vfp,
                 float* __restrict__ out, int nrows) {
    extern __shared__ __align__(16) char smem_c[];
    const uint32_t smem_base = smem_u32(smem_c);
    const int tid  = threadIdx.x;
    const int warp = tid >> 5, lane = tid & 31;
    const int row0 = blockIdx.x * ROWS_CTA;

    // ---- copy v split images (linear; only CTA-wide barrier in the kernel) ----
    {
        const float4* vg = (const float4*)g_vimg;
        float4* vs = (float4*)(smem_c + B_OFF);
        for (int i = tid; i < 2 * BIMG / 16; i += THREADS) vs[i] = vg[i];
    }
    __syncthreads();

    // ---- per-warp HMMA: 16 rows x 128 cols, A frags built from GMEM x ----
    const int wr0 = warp * RPW;
    const int r4 = lane >> 2, q4 = lane & 3;
    const int k0 = q4 * 2;
    const int grow0 = row0 + wr0 + r4;
    const int grow8 = grow0 + 8;
    const float* xr0 = x + (size_t)grow0 * DIM;
    const float* xr8 = x + (size_t)grow8 * DIM;
    const bool p0 = grow0 < nrows;
    const bool p8 = grow8 < nrows;

    const int g = lane >> 3, lr = lane & 7;
    const uint32_t b_addr = smem_base + B_OFF +
        (uint32_t)((lr + (g >> 1) * 8) * APITCH + (g & 1) * 8) * 2;

    float C[16][4];
    #pragma unroll
    for (int i = 0; i < 16; i++)
        #pragma unroll
        for (int j = 0; j < 4; j++) C[i][j] = 0.f;

    #pragma unroll
    for (int k = 0; k < 8; ++k) {
        const int kb = k * 16;
        float2 v00 = p0 ? *(const float2*)(xr0 + kb + k0)     : make_float2(0.f, 0.f);
        float2 v80 = p8 ? *(const float2*)(xr8 + kb + k0)     : make_float2(0.f, 0.f);
        float2 v01 = p0 ? *(const float2*)(xr0 + kb + k0 + 8) : make_float2(0.f, 0.f);
        float2 v81 = p8 ? *(const float2*)(xr8 + kb + k0 + 8) : make_float2(0.f, 0.f);
        uint32_t A0[4], A1[4];
        split_pair(v00, A0[0], A1[0]);
        split_pair(v80, A0[1], A1[1]);
        split_pair(v01, A0[2], A1[2]);
        split_pair(v81, A0[3], A1[3]);
        #pragma unroll
        for (int nt = 0; nt < 8; ++nt) {
            uint32_t B0[4], B1[4];
            ldm_x4(b_addr + 0 * BIMG + nt * (16 * APITCH * 2) + k * 32, B0);
            ldm_x4(b_addr + 1 * BIMG + nt * (16 * APITCH * 2) + k * 32, B1);
            float* c0 = C[2 * nt];
            float* c1 = C[2 * nt + 1];
            mma_f16(c0, A0, B0[0], B0[1]);  mma_f16(c1, A0, B0[2], B0[3]);
            mma_f16(c0, A0, B1[0], B1[1]);  mma_f16(c1, A0, B1[2], B1[3]);
            mma_f16(c0, A1, B0[0], B0[1]);  mma_f16(c1, A1, B0[2], B0[3]);
        }
    }

    // ---- per-warp: stage 8 rows of y, select (4-row interleave), output ----
    const float inv_len = g_inv_len;
    float* yw = (float*)(smem_c + Y_OFF + warp * YCHUNK);
    uint2* st = (uint2*)(smem_c + ST_OFF) + warp * 4 * KSEL;
    int* candw = (int*)(smem_c + CAND_OFF) + warp * 64;
    const int col0 = (31 - lane) * 4;           // FLO(ballot) -> lowest column

    #pragma unroll
    for (int half = 0; half < 2; ++half) {
        // stage this half's 8 rows (C regs -> SMEM)
        #pragma unroll
        for (int nt = 0; nt < 16; ++nt) {
            float2 val = half == 0 ? make_float2(C[nt][0], C[nt][1])
                                   : make_float2(C[nt][2], C[nt][3]);
            *(float2*)(yw + r4 * YPITCH + nt * 8 + 2 * q4) = val;
        }
        __syncwarp();

        #pragma unroll 1
        for (int grp = 0; grp < 2; ++grp) {
            unsigned kk[4][4], cc[4][4];
            #pragma unroll
            for (int j = 0; j < 4; ++j) {
                int rowl = grp * 4 + j;                 // chunk-local 0..7
                float4 y4 = *(const float4*)(yw + rowl * YPITCH + col0);
                kk[j][0] = fkey(y4.x); kk[j][1] = fkey(y4.y);
                kk[j][2] = fkey(y4.z); kk[j][3] = fkey(y4.w);
                cc[j][0] = col0 + 0; cc[j][1] = col0 + 1;
                cc[j][2] = col0 + 2; cc[j][3] = col0 + 3;
                CSWAP(kk[j][0], cc[j][0], kk[j][1], cc[j][1]);
                CSWAP(kk[j][2], cc[j][2], kk[j][3], cc[j][3]);
                CSWAP(kk[j][0], cc[j][0], kk[j][2], cc[j][2]);
                CSWAP(kk[j][1], cc[j][1], kk[j][3], cc[j][3]);
                CSWAP(kk[j][1], cc[j][1], kk[j][2], cc[j][2]);
            }

            #pragma unroll 4
            for (int i = 0; i < KSEL; ++i) {
                #pragma unroll
                for (int j = 0; j < 4; ++j) {
                    unsigned m   = __reduce_max_sync(0xffffffffu, kk[j][0]);
                    unsigned bal = __ballot_sync(0xffffffffu, kk[j][0] == m);
                    bool win = (lane == 31 - __clz(bal));
                    if (win) st[j * KSEL + i] = make_uint2(cc[j][0], kk[j][0]);
                    kk[j][0] = win ? kk[j][1] : kk[j][0];  cc[j][0] = win ? cc[j][1] : cc[j][0];
                    kk[j][1] = win ? kk[j][2] : kk[j][1];  cc[j][1] = win ? cc[j][2] : cc[j][1];
                    kk[j][2] = win ? kk[j][3] : kk[j][2];  cc[j][2] = win ? cc[j][3] : cc[j][2];
                    kk[j][3] = win ? 0u       : kk[j][3];
                }
            }
            __syncwarp();

            // ---- gap check, rare exact fixup, output ----
            #pragma unroll
            for (int j = 0; j < 4; ++j) {
                const int rowl = grp * 4 + j;
                const int grow = row0 + wr0 + half * 8 + rowl;
                if (grow < nrows) {
                    uint2 p = st[j * KSEL + lane];
                    float yl = unfkey(p.y);
                    float y33 = unfkey(__reduce_max_sync(0xffffffffu, kk[j][0]));
                    float ynext = __shfl_down_sync(0xffffffffu, yl, 1);
                    if (lane == 31) ynext = y33;
                    if (__ballot_sync(0xffffffffu, (yl - ynext) < TAU)) {
                        float y31 = __shfl_sync(0xffffffffu, yl, 31);
                        fixup_row(x, vfp, grow, yw + rowl * YPITCH,
                                  st + j * KSEL, candw, y31);
                        p = st[j * KSEL + lane];
                    }
                    float d  = unfkey(p.y) * inv_len;
                    float sg = 1.0f / (1.0f + __expf(-d));
                    float xv = __ldg(&x[(size_t)grow * DIM + p.x]);
                    out[(size_t)grow * KSEL + lane] = xv * sg;
                }
                __syncwarp();
            }
        }
    }
}

// ---------------------------------------------------------------------------
extern "C" void kernel_launch(void* const* d_in, const int* in_sizes, int n_in,
                              void* d_out, int out_size) {
    const float* x = (const float*)d_in[0];
    const float* v = (const float*)d_in[1];
    float* out = (float*)d_out;
    const int nrows = in_sizes[0] / DIM;

    cudaFuncSetAttribute(pool_kernel,
                         cudaFuncAttributeMaxDynamicSharedMemorySize, SMEM_TOTAL);

    prep_kernel<<<1, 256>>>(v);
    const int grid = (nrows + ROWS_CTA - 1) / ROWS_CTA;
    pool_kernel<<<grid, THREADS, SMEM_TOTAL>>>(x, v, out, nrows);
}

// round 15
// speedup vs baseline: 1.2236x; 1.0533x over previous
#include <cuda_runtime.h>
#include <cuda_fp16.h>
#include <cstdint>
#include <cstddef>

#define DIM       128
#define ROWS_CTA  128
#define THREADS   256
#define RPW       16                    // rows per warp (gemm)
#define KSEL      32
#define APITCH    136                   // fp16 elems per B row (272 B)
#define BIMG      (DIM*APITCH*2)        // 34816 B per v split image
#define SMEM_A    (2*BIMG)              // 69632 -> 2 CTAs/SM (reg-limited anyway)
#define TAU       1e-4f                 // ~25 sigma of fp16 2-split error
#define MAXROWS   500096                // 3907 * 128

__device__ float g_inv_len;
__device__ __align__(16) unsigned char g_vimg[2][BIMG];
__device__ float g_y[(size_t)MAXROWS * DIM];   // 256MB scratch (static, allowed)

// ---------------------------------------------------------------------------
__device__ __forceinline__ uint32_t smem_u32(const void* p) {
    uint32_t a;
    asm("{ .reg .u64 t; cvta.to.shared.u64 t, %1; cvt.u32.u64 %0, t; }"
        : "=r"(a) : "l"(p));
    return a;
}
__device__ __forceinline__ unsigned fkey(float f) {
    unsigned u = __float_as_uint(f);
    return (u & 0x80000000u) ? ~u : (u | 0x80000000u);
}
__device__ __forceinline__ float unfkey(unsigned m) {
    unsigned u = (m & 0x80000000u) ? (m & 0x7fffffffu) : ~m;
    return __uint_as_float(u);
}
#define CSWAP(ka, ca, kb, cb)                                   \
    {                                                           \
        bool sw = (ka < kb) || (ka == kb && ca > cb);           \
        unsigned tk_ = sw ? kb : ka;                            \
        unsigned tc_ = sw ? cb : ca;                            \
        kb = sw ? ka : kb;  cb = sw ? ca : cb;                  \
        ka = tk_;           ca = tc_;                           \
    }

__device__ __forceinline__ void ldm_x4(uint32_t addr, uint32_t* r) {
    asm volatile("ldmatrix.sync.aligned.m8n8.x4.shared.b16 {%0,%1,%2,%3}, [%4];"
                 : "=r"(r[0]), "=r"(r[1]), "=r"(r[2]), "=r"(r[3]) : "r"(addr));
}
__device__ __forceinline__ void mma_f16(float* c, const uint32_t* a,
                                        uint32_t b0, uint32_t b1) {
    asm volatile(
        "mma.sync.aligned.m16n8k16.row.col.f32.f16.f16.f32 "
        "{%0,%1,%2,%3}, {%4,%5,%6,%7}, {%8,%9}, {%0,%1,%2,%3};"
        : "+f"(c[0]), "+f"(c[1]), "+f"(c[2]), "+f"(c[3])
        : "r"(a[0]), "r"(a[1]), "r"(a[2]), "r"(a[3]), "r"(b0), "r"(b1));
}
// fp16 2-split of a float pair: h0 = rn(v), h1 = rn(v - f32(h0)); (lo=x, hi=y)
__device__ __forceinline__ void split_pair(float2 v, uint32_t& h0, uint32_t& h1) {
    asm("cvt.rn.f16x2.f32 %0, %1, %2;" : "=r"(h0) : "f"(v.y), "f"(v.x));
    float bx, by;
    asm("{\n\t.reg .b16 l, h;\n\tmov.b32 {l, h}, %2;\n\t"
        "cvt.f32.f16 %0, l;\n\tcvt.f32.f16 %1, h;\n\t}"
        : "=f"(bx), "=f"(by) : "r"(h0));
    asm("cvt.rn.f16x2.f32 %0, %1, %2;" : "=r"(h1) : "f"(v.y - by), "f"(v.x - bx));
}

// ---------------------------------------------------------------------------
// prep: 1/||v|| and fp16 2-split images of B[n][k] = v[k][n]
// ---------------------------------------------------------------------------
__global__ void prep_kernel(const float* __restrict__ v) {
    __shared__ float red[8];
    const int tid = threadIdx.x;
    float s = 0.f;
    for (int i = tid; i < DIM * DIM; i += 256) { float a = v[i]; s = fmaf(a, a, s); }
    #pragma unroll
    for (int o = 16; o; o >>= 1) s += __shfl_xor_sync(0xffffffffu, s, o);
    if ((tid & 31) == 0) red[tid >> 5] = s;
    __syncthreads();
    if (tid == 0) {
        float t = 0.f;
        #pragma unroll
        for (int i = 0; i < 8; i++) t += red[i];
        g_inv_len = 1.0f / sqrtf(t);
    }
    for (int i = tid; i < DIM * DIM; i += 256) {
        int k = i >> 7, n = i & 127;
        float a = v[i];
        __half h0 = __float2half_rn(a);
        float r1 = a - __half2float(h0);
        uint32_t off = (uint32_t)(n * APITCH + k) * 2;
        *(__half*)(g_vimg[0] + off) = h0;
        *(__half*)(g_vimg[1] + off) = __float2half_rn(r1);
    }
}

// ---------------------------------------------------------------------------
// Kernel A: warp-autonomous fp16 2-split HMMA (3 products) -> y (GMEM)
// ---------------------------------------------------------------------------
__global__ __launch_bounds__(THREADS, 2)
void gemm_kernel(const float* __restrict__ x, int nrows) {
    extern __shared__ __align__(16) char smem_c[];
    const uint32_t smem_base = smem_u32(smem_c);
    const int tid  = threadIdx.x;
    const int warp = tid >> 5, lane = tid & 31;
    const int row0 = blockIdx.x * ROWS_CTA;

    // copy v split images (linear; only CTA barrier in the kernel)
    {
        const float4* vg = (const float4*)g_vimg;
        float4* vs = (float4*)smem_c;
        for (int i = tid; i < 2 * BIMG / 16; i += THREADS) vs[i] = vg[i];
    }
    __syncthreads();

    const int wr0 = warp * RPW;
    const int r4 = lane >> 2, q4 = lane & 3;
    const int k0 = q4 * 2;
    const int grow0 = row0 + wr0 + r4;
    const int grow8 = grow0 + 8;
    const float* xr0 = x + (size_t)grow0 * DIM;
    const float* xr8 = x + (size_t)grow8 * DIM;
    const bool p0 = grow0 < nrows;
    const bool p8 = grow8 < nrows;

    const int g = lane >> 3, lr = lane & 7;
    const uint32_t b_addr = smem_base +
        (uint32_t)((lr + (g >> 1) * 8) * APITCH + (g & 1) * 8) * 2;

    float C[16][4];
    #pragma unroll
    for (int i = 0; i < 16; i++)
        #pragma unroll
        for (int j = 0; j < 4; j++) C[i][j] = 0.f;

    #pragma unroll
    for (int k = 0; k < 8; ++k) {
        const int kb = k * 16;
        float2 v00 = p0 ? *(const float2*)(xr0 + kb + k0)     : make_float2(0.f, 0.f);
        float2 v80 = p8 ? *(const float2*)(xr8 + kb + k0)     : make_float2(0.f, 0.f);
        float2 v01 = p0 ? *(const float2*)(xr0 + kb + k0 + 8) : make_float2(0.f, 0.f);
        float2 v81 = p8 ? *(const float2*)(xr8 + kb + k0 + 8) : make_float2(0.f, 0.f);
        uint32_t A0[4], A1[4];
        split_pair(v00, A0[0], A1[0]);
        split_pair(v80, A0[1], A1[1]);
        split_pair(v01, A0[2], A1[2]);
        split_pair(v81, A0[3], A1[3]);
        #pragma unroll
        for (int nt = 0; nt < 8; ++nt) {
            uint32_t B0[4], B1[4];
            ldm_x4(b_addr + 0 * BIMG + nt * (16 * APITCH * 2) + k * 32, B0);
            ldm_x4(b_addr + 1 * BIMG + nt * (16 * APITCH * 2) + k * 32, B1);
            float* c0 = C[2 * nt];
            float* c1 = C[2 * nt + 1];
            mma_f16(c0, A0, B0[0], B0[1]);  mma_f16(c1, A0, B0[2], B0[3]);
            mma_f16(c0, A0, B1[0], B1[1]);  mma_f16(c1, A0, B1[2], B1[3]);
            mma_f16(c0, A1, B0[0], B0[1]);  mma_f16(c1, A1, B0[2], B0[3]);
        }
    }

    // write y fragments to GMEM: C[j][0..1] -> row grow0, C[j][2..3] -> grow8
    float* yr0 = g_y + (size_t)grow0 * DIM + 2 * q4;
    float* yr8 = g_y + (size_t)grow8 * DIM + 2 * q4;
    #pragma unroll
    for (int j = 0; j < 16; ++j) {
        if (p0) *(float2*)(yr0 + j * 8) = make_float2(C[j][0], C[j][1]);
        if (p8) *(float2*)(yr8 + j * 8) = make_float2(C[j][2], C[j][3]);
    }
}

// ---------------------------------------------------------------------------
// rare-path fixup: exact (ascending-k fp32 fma) re-rank of ambiguous rows
// ---------------------------------------------------------------------------
__device__ __noinline__ void fixup_row(const float* __restrict__ x,
                                       const float* __restrict__ vfp,
                                       int grow, const float* __restrict__ yrow,
                                       uint2* st_row, int* candbuf, float y31) {
    const int lane = threadIdx.x & 31;
    const int col0 = (31 - lane) * 4;
    const float yt = y31 - TAU;

    int base = 0;
    #pragma unroll
    for (int q = 0; q < 4; ++q) {
        int c = col0 + q;
        bool sel = (__ldg(yrow + c) >= yt);
        unsigned bal = __ballot_sync(0xffffffffu, sel);
        int pos = base + __popc(bal & ((1u << lane) - 1u));
        if (sel && pos < 64) candbuf[pos] = c;
        base += __popc(bal);
    }
    int ncand = base < 64 ? base : 64;
    __syncwarp();

    int c1 = (lane < ncand) ? candbuf[lane] : -1;
    int c2 = (lane + 32 < ncand) ? candbuf[lane + 32] : -1;
    const float* xr = x + (size_t)grow * DIM;
    const float* v1 = vfp + ((c1 >= 0) ? c1 : 0);
    const float* v2 = vfp + ((c2 >= 0) ? c2 : 0);
    float a1 = 0.f, a2 = 0.f;
    #pragma unroll 4
    for (int k = 0; k < DIM; ++k) {
        float xv = __ldg(xr + k);
        a1 = fmaf(xv, __ldg(v1 + (size_t)k * DIM), a1);
        a2 = fmaf(xv, __ldg(v2 + (size_t)k * DIM), a2);
    }

    unsigned hk = (c1 >= 0) ? fkey(a1) : 0u;
    unsigned hc = (c1 >= 0) ? (unsigned)c1 : 0x7fffffffu;
    unsigned tk = (c2 >= 0) ? fkey(a2) : 0u;
    unsigned tc = (c2 >= 0) ? (unsigned)c2 : 0x7fffffffu;
    CSWAP(hk, hc, tk, tc);

    #pragma unroll 1
    for (int i = 0; i < KSEL; ++i) {
        unsigned m = __reduce_max_sync(0xffffffffu, hk);
        bool sel = (hk == m);
        unsigned colx = sel ? hc : 0x7fffffffu;
        unsigned minc = __reduce_min_sync(0xffffffffu, colx);   // jax tie-break
        bool win = sel && (hc == minc);
        if (win) st_row[i] = make_uint2(hc, hk);
        hk = win ? tk : hk;  hc = win ? tc : hc;  tk = win ? 0u : tk;
    }
    __syncwarp();
}

// ---------------------------------------------------------------------------
// Kernel B: high-occupancy top-32 selection from y (2-row ILP, R11 style)
// ---------------------------------------------------------------------------
__global__ __launch_bounds__(THREADS)
void sel_kernel(const float* __restrict__ x, const float* __restrict__ vfp,
                float* __restrict__ out, int nrows) {
    __shared__ uint2 st_s[8][2 * KSEL];
    __shared__ int   cand_s[8][64];

    const int tid  = threadIdx.x;
    const int warp = tid >> 5, lane = tid & 31;
    const int rbase = (blockIdx.x * 8 + warp) * 8;   // 8 rows per warp
    const int col0 = (31 - lane) * 4;                // FLO(ballot) -> lowest col
    const float inv_len = g_inv_len;
    uint2* stA = st_s[warp];
    uint2* stB = stA + KSEL;
    int* candw = cand_s[warp];

    #pragma unroll 1
    for (int pr = 0; pr < 4; ++pr) {
        const int rA = rbase + 2 * pr;
        if (rA >= nrows) break;                      // warp-uniform
        const bool hasB = (rA + 1 < nrows);

        float4 ya = *(const float4*)(g_y + (size_t)rA * DIM + col0);
        float4 yb = hasB ? *(const float4*)(g_y + (size_t)(rA + 1) * DIM + col0)
                         : make_float4(0.f, 0.f, 0.f, 0.f);

        unsigned kA0 = fkey(ya.x), kA1 = fkey(ya.y), kA2 = fkey(ya.z), kA3 = fkey(ya.w);
        unsigned kB0 = fkey(yb.x), kB1 = fkey(yb.y), kB2 = fkey(yb.z), kB3 = fkey(yb.w);
        unsigned cA0 = col0 + 0, cA1 = col0 + 1, cA2 = col0 + 2, cA3 = col0 + 3;
        unsigned cB0 = cA0, cB1 = cA1, cB2 = cA2, cB3 = cA3;

        CSWAP(kA0, cA0, kA1, cA1); CSWAP(kA2, cA2, kA3, cA3);
        CSWAP(kA0, cA0, kA2, cA2); CSWAP(kA1, cA1, kA3, cA3);
        CSWAP(kA1, cA1, kA2, cA2);
        CSWAP(kB0, cB0, kB1, cB1); CSWAP(kB2, cB2, kB3, cB3);
        CSWAP(kB0, cB0, kB2, cB2); CSWAP(kB1, cB1, kB3, cB3);
        CSWAP(kB1, cB1, kB2, cB2);

        #pragma unroll 4
        for (int i = 0; i < KSEL; ++i) {
            unsigned mA = __reduce_max_sync(0xffffffffu, kA0);
            unsigned mB = __reduce_max_sync(0xffffffffu, kB0);
            unsigned balA = __ballot_sync(0xffffffffu, kA0 == mA);
            unsigned balB = __ballot_sync(0xffffffffu, kB0 == mB);
            bool winA = (lane == 31 - __clz(balA));
            bool winB = (lane == 31 - __clz(balB));
            if (winA) stA[i] = make_uint2(cA0, kA0);
            if (winB) stB[i] = make_uint2(cB0, kB0);
            kA0 = winA ? kA1 : kA0;  cA0 = winA ? cA1 : cA0;
            kA1 = winA ? kA2 : kA1;  cA1 = winA ? cA2 : cA1;
            kA2 = winA ? kA3 : kA2;  cA2 = winA ? cA3 : cA2;
            kA3 = winA ? 0u  : kA3;
            kB0 = winB ? kB1 : kB0;  cB0 = winB ? cB1 : cB0;
            kB1 = winB ? kB2 : kB1;  cB1 = winB ? cB2 : cB1;
            kB2 = winB ? kB3 : kB2;  cB2 = winB ? cB3 : cB2;
            kB3 = winB ? 0u  : kB3;
        }
        __syncwarp();

        // row A: gap check, rare fixup, output
        {
            uint2 p = stA[lane];
            float yl = unfkey(p.y);
            float y33 = unfkey(__reduce_max_sync(0xffffffffu, kA0));
            float ynext = __shfl_down_sync(0xffffffffu, yl, 1);
            if (lane == 31) ynext = y33;
            if (__ballot_sync(0xffffffffu, (yl - ynext) < TAU)) {
                float y31 = __shfl_sync(0xffffffffu, yl, 31);
                fixup_row(x, vfp, rA, g_y + (size_t)rA * DIM, stA, candw, y31);
                p = stA[lane];
            }
            float d  = unfkey(p.y) * inv_len;
            float sg = 1.0f / (1.0f + __expf(-d));
            float xv = __ldg(&x[(size_t)rA * DIM + p.x]);
            out[(size_t)rA * KSEL + lane] = xv * sg;
        }
        // row B
        if (hasB) {
            uint2 p = stB[lane];
            float yl = unfkey(p.y);
            float y33 = unfkey(__reduce_max_sync(0xffffffffu, kB0));
            float ynext = __shfl_down_sync(0xffffffffu, yl, 1);
            if (lane == 31) ynext = y33;
            if (__ballot_sync(0xffffffffu, (yl - ynext) < TAU)) {
                float y31 = __shfl_sync(0xffffffffu, yl, 31);
                fixup_row(x, vfp, rA + 1, g_y + (size_t)(rA + 1) * DIM, stB, candw, y31);
                p = stB[lane];
            }
            float d  = unfkey(p.y) * inv_len;
            float sg = 1.0f / (1.0f + __expf(-d));
            float xv = __ldg(&x[(size_t)(rA + 1) * DIM + p.x]);
            out[(size_t)(rA + 1) * KSEL + lane] = xv * sg;
        }
        __syncwarp();
    }
}

// ---------------------------------------------------------------------------
extern "C" void kernel_launch(void* const* d_in, const int* in_sizes, int n_in,
                              void* d_out, int out_size) {
    const float* x = (const float*)d_in[0];
    const float* v = (const float*)d_in[1];
    float* out = (float*)d_out;
    const int nrows = in_sizes[0] / DIM;

    cudaFuncSetAttribute(gemm_kernel,
                         cudaFuncAttributeMaxDynamicSharedMemorySize, SMEM_A);

    prep_kernel<<<1, 256>>>(v);
    const int grid_a = (nrows + ROWS_CTA - 1) / ROWS_CTA;
    gemm_kernel<<<grid_a, THREADS, SMEM_A>>>(x, nrows);
    const int grid_b = (nrows + 63) / 64;
    sel_kernel<<<grid_b, THREADS>>>(x, v, out, nrows);
}

// round 16
// speedup vs baseline: 1.2250x; 1.0012x over previous
#include <cuda_runtime.h>
#include <cuda_fp16.h>
#include <cstdint>
#include <cstddef>

#define DIM       128
#define ROWS_CTA  128
#define THREADS   256
#define RPW       16                    // rows per warp (gemm)
#define KSEL      32
#define APITCH    136                   // fp16 elems per B row (272 B)
#define BIMG      (DIM*APITCH*2)        // 34816 B per v split image
#define SMEM_A    (2*BIMG)              // 69632
#define MAXROWS   500096                // 3907 * 128

__device__ float g_inv_len;
__device__ float g_partial[64];
__device__ __align__(16) unsigned char g_vimg[2][BIMG];
__device__ float g_y[(size_t)MAXROWS * DIM];   // 256MB scratch (static, allowed)

// ---------------------------------------------------------------------------
__device__ __forceinline__ uint32_t smem_u32(const void* p) {
    uint32_t a;
    asm("{ .reg .u64 t; cvta.to.shared.u64 t, %1; cvt.u32.u64 %0, t; }"
        : "=r"(a) : "l"(p));
    return a;
}
__device__ __forceinline__ unsigned fkey(float f) {
    unsigned u = __float_as_uint(f);
    return (u & 0x80000000u) ? ~u : (u | 0x80000000u);
}
__device__ __forceinline__ float unfkey(unsigned m) {
    unsigned u = (m & 0x80000000u) ? (m & 0x7fffffffu) : ~m;
    return __uint_as_float(u);
}
#define CSWAP(ka, ca, kb, cb)                                   \
    {                                                           \
        bool sw = (ka < kb) || (ka == kb && ca > cb);           \
        unsigned tk_ = sw ? kb : ka;                            \
        unsigned tc_ = sw ? cb : ca;                            \
        kb = sw ? ka : kb;  cb = sw ? ca : cb;                  \
        ka = tk_;           ca = tc_;                           \
    }
// single-value desc compare-exchange (packed keys are unique)
#define KSWAP(a, b) { unsigned hi_ = max(a, b), lo_ = min(a, b); a = hi_; b = lo_; }

__device__ __forceinline__ void ldm_x4(uint32_t addr, uint32_t* r) {
    asm volatile("ldmatrix.sync.aligned.m8n8.x4.shared.b16 {%0,%1,%2,%3}, [%4];"
                 : "=r"(r[0]), "=r"(r[1]), "=r"(r[2]), "=r"(r[3]) : "r"(addr));
}
__device__ __forceinline__ void mma_f16(float* c, const uint32_t* a,
                                        uint32_t b0, uint32_t b1) {
    asm volatile(
        "mma.sync.aligned.m16n8k16.row.col.f32.f16.f16.f32 "
        "{%0,%1,%2,%3}, {%4,%5,%6,%7}, {%8,%9}, {%0,%1,%2,%3};"
        : "+f"(c[0]), "+f"(c[1]), "+f"(c[2]), "+f"(c[3])
        : "r"(a[0]), "r"(a[1]), "r"(a[2]), "r"(a[3]), "r"(b0), "r"(b1));
}
__device__ __forceinline__ void split_pair(float2 v, uint32_t& h0, uint32_t& h1) {
    asm("cvt.rn.f16x2.f32 %0, %1, %2;" : "=r"(h0) : "f"(v.y), "f"(v.x));
    float bx, by;
    asm("{\n\t.reg .b16 l, h;\n\tmov.b32 {l, h}, %2;\n\t"
        "cvt.f32.f16 %0, l;\n\tcvt.f32.f16 %1, h;\n\t}"
        : "=f"(bx), "=f"(by) : "r"(h0));
    asm("cvt.rn.f16x2.f32 %0, %1, %2;" : "=r"(h1) : "f"(v.y - by), "f"(v.x - bx));
}

// ---------------------------------------------------------------------------
// prep (parallel): fp16 2-split images of B[n][k]=v[k][n] + partial norms
// ---------------------------------------------------------------------------
__global__ void prep_split(const float* __restrict__ v) {
    __shared__ float red[8];
    const int tid = threadIdx.x;
    const int i = blockIdx.x * 256 + tid;     // 64 blocks x 256 = 16384
    float a = v[i];
    float s = a * a;
    #pragma unroll
    for (int o = 16; o; o >>= 1) s += __shfl_xor_sync(0xffffffffu, s, o);
    if ((tid & 31) == 0) red[tid >> 5] = s;
    __syncthreads();
    if (tid == 0) {
        float t = 0.f;
        #pragma unroll
        for (int w = 0; w < 8; w++) t += red[w];
        g_partial[blockIdx.x] = t;
    }
    int k = i >> 7, n = i & 127;
    __half h0 = __float2half_rn(a);
    float r1 = a - __half2float(h0);
    uint32_t off = (uint32_t)(n * APITCH + k) * 2;
    *(__half*)(g_vimg[0] + off) = h0;
    *(__half*)(g_vimg[1] + off) = __float2half_rn(r1);
}
__global__ void prep_finalize() {
    const int tid = threadIdx.x;              // 64 threads
    __shared__ float red[2];
    float s = g_partial[tid];
    #pragma unroll
    for (int o = 16; o; o >>= 1) s += __shfl_xor_sync(0xffffffffu, s, o);
    if ((tid & 31) == 0) red[tid >> 5] = s;
    __syncthreads();
    if (tid == 0) g_inv_len = 1.0f / sqrtf(red[0] + red[1]);
}

// ---------------------------------------------------------------------------
// Kernel A: warp-autonomous fp16 2-split HMMA (3 products) -> y (GMEM)
// ---------------------------------------------------------------------------
__global__ __launch_bounds__(THREADS, 2)
void gemm_kernel(const float* __restrict__ x, int nrows) {
    extern __shared__ __align__(16) char smem_c[];
    const uint32_t smem_base = smem_u32(smem_c);
    const int tid  = threadIdx.x;
    const int warp = tid >> 5, lane = tid & 31;
    const int row0 = blockIdx.x * ROWS_CTA;

    {
        const float4* vg = (const float4*)g_vimg;
        float4* vs = (float4*)smem_c;
        for (int i = tid; i < 2 * BIMG / 16; i += THREADS) vs[i] = vg[i];
    }
    __syncthreads();

    const int wr0 = warp * RPW;
    const int r4 = lane >> 2, q4 = lane & 3;
    const int k0 = q4 * 2;
    const int grow0 = row0 + wr0 + r4;
    const int grow8 = grow0 + 8;
    const float* xr0 = x + (size_t)grow0 * DIM;
    const float* xr8 = x + (size_t)grow8 * DIM;
    const bool p0 = grow0 < nrows;
    const bool p8 = grow8 < nrows;

    const int g = lane >> 3, lr = lane & 7;
    const uint32_t b_addr = smem_base +
        (uint32_t)((lr + (g >> 1) * 8) * APITCH + (g & 1) * 8) * 2;

    float C[16][4];
    #pragma unroll
    for (int i = 0; i < 16; i++)
        #pragma unroll
        for (int j = 0; j < 4; j++) C[i][j] = 0.f;

    #pragma unroll
    for (int k = 0; k < 8; ++k) {
        const int kb = k * 16;
        float2 v00 = p0 ? *(const float2*)(xr0 + kb + k0)     : make_float2(0.f, 0.f);
        float2 v80 = p8 ? *(const float2*)(xr8 + kb + k0)     : make_float2(0.f, 0.f);
        float2 v01 = p0 ? *(const float2*)(xr0 + kb + k0 + 8) : make_float2(0.f, 0.f);
        float2 v81 = p8 ? *(const float2*)(xr8 + kb + k0 + 8) : make_float2(0.f, 0.f);
        uint32_t A0[4], A1[4];
        split_pair(v00, A0[0], A1[0]);
        split_pair(v80, A0[1], A1[1]);
        split_pair(v01, A0[2], A1[2]);
        split_pair(v81, A0[3], A1[3]);
        #pragma unroll
        for (int nt = 0; nt < 8; ++nt) {
            uint32_t B0[4], B1[4];
            ldm_x4(b_addr + 0 * BIMG + nt * (16 * APITCH * 2) + k * 32, B0);
            ldm_x4(b_addr + 1 * BIMG + nt * (16 * APITCH * 2) + k * 32, B1);
            float* c0 = C[2 * nt];
            float* c1 = C[2 * nt + 1];
            mma_f16(c0, A0, B0[0], B0[1]);  mma_f16(c1, A0, B0[2], B0[3]);
            mma_f16(c0, A0, B1[0], B1[1]);  mma_f16(c1, A0, B1[2], B1[3]);
            mma_f16(c0, A1, B0[0], B0[1]);  mma_f16(c1, A1, B0[2], B0[3]);
        }
    }

    float* yr0 = g_y + (size_t)grow0 * DIM + 2 * q4;
    float* yr8 = g_y + (size_t)grow8 * DIM + 2 * q4;
    #pragma unroll
    for (int j = 0; j < 16; ++j) {
        if (p0) *(float2*)(yr0 + j * 8) = make_float2(C[j][0], C[j][1]);
        if (p8) *(float2*)(yr8 + j * 8) = make_float2(C[j][2], C[j][3]);
    }
}

// ---------------------------------------------------------------------------
// rare-path fixup: exact (ascending-k fp32 fma) re-rank of ambiguous rows
// ---------------------------------------------------------------------------
__device__ __noinline__ void fixup_row(const float* __restrict__ x,
                                       const float* __restrict__ vfp,
                                       int grow, const float* __restrict__ yrow,
                                       uint2* st_row, int* candbuf, float yt) {
    const int lane = threadIdx.x & 31;
    const int col0 = lane * 4;

    int base = 0;
    #pragma unroll
    for (int q = 0; q < 4; ++q) {
        int c = col0 + q;
        bool sel = (__ldg(yrow + c) >= yt);
        unsigned bal = __ballot_sync(0xffffffffu, sel);
        int pos = base + __popc(bal & ((1u << lane) - 1u));
        if (sel && pos < 64) candbuf[pos] = c;
        base += __popc(bal);
    }
    int ncand = base < 64 ? base : 64;
    __syncwarp();

    int c1 = (lane < ncand) ? candbuf[lane] : -1;
    int c2 = (lane + 32 < ncand) ? candbuf[lane + 32] : -1;
    const float* xr = x + (size_t)grow * DIM;
    const float* v1 = vfp + ((c1 >= 0) ? c1 : 0);
    const float* v2 = vfp + ((c2 >= 0) ? c2 : 0);
    float a1 = 0.f, a2 = 0.f;
    #pragma unroll 4
    for (int k = 0; k < DIM; ++k) {
        float xv = __ldg(xr + k);
        a1 = fmaf(xv, __ldg(v1 + (size_t)k * DIM), a1);
        a2 = fmaf(xv, __ldg(v2 + (size_t)k * DIM), a2);
    }

    unsigned hk = (c1 >= 0) ? fkey(a1) : 0u;
    unsigned hc = (c1 >= 0) ? (unsigned)c1 : 0x7fffffffu;
    unsigned tk = (c2 >= 0) ? fkey(a2) : 0u;
    unsigned tc = (c2 >= 0) ? (unsigned)c2 : 0x7fffffffu;
    CSWAP(hk, hc, tk, tc);

    #pragma unroll 1
    for (int i = 0; i < KSEL; ++i) {
        unsigned m = __reduce_max_sync(0xffffffffu, hk);
        bool sel = (hk == m);
        unsigned colx = sel ? hc : 0x7fffffffu;
        unsigned minc = __reduce_min_sync(0xffffffffu, colx);   // jax tie-break
        bool win = sel && (hc == minc);
        if (win) st_row[i] = make_uint2(hc, hk);
        hk = win ? tk : hk;  hc = win ? tc : hc;  tk = win ? 0u : tk;
    }
    __syncwarp();
}

// ---------------------------------------------------------------------------
// Kernel B: packed-key top-32 selection (no ballot, no SMEM stage fast path)
//   pk = (fkey(y) & ~127) | (127 - col)  -> unique keys, jax tie-break built in
// ---------------------------------------------------------------------------
__global__ __launch_bounds__(THREADS)
void sel_kernel(const float* __restrict__ x, const float* __restrict__ vfp,
                float* __restrict__ out, int nrows) {
    __shared__ uint2 st_s[8][2 * KSEL];
    __shared__ int   cand_s[8][64];

    const int tid  = threadIdx.x;
    const int warp = tid >> 5, lane = tid & 31;
    const int rbase = (blockIdx.x * 8 + warp) * 8;   // 8 rows per warp
    const int col0 = lane * 4;
    const float inv_len = g_inv_len;
    uint2* stA = st_s[warp];
    uint2* stB = stA + KSEL;
    int* candw = cand_s[warp];

    #pragma unroll 1
    for (int pr = 0; pr < 4; ++pr) {
        const int rA = rbase + 2 * pr;
        if (rA >= nrows) break;                      // warp-uniform
        const bool hasB = (rA + 1 < nrows);

        float4 ya = *(const float4*)(g_y + (size_t)rA * DIM + col0);
        float4 yb = hasB ? *(const float4*)(g_y + (size_t)(rA + 1) * DIM + col0)
                         : make_float4(0.f, 0.f, 0.f, 0.f);

        unsigned kA0 = (fkey(ya.x) & 0xFFFFFF80u) | (unsigned)(127 - col0);
        unsigned kA1 = (fkey(ya.y) & 0xFFFFFF80u) | (unsigned)(126 - col0);
        unsigned kA2 = (fkey(ya.z) & 0xFFFFFF80u) | (unsigned)(125 - col0);
        unsigned kA3 = (fkey(ya.w) & 0xFFFFFF80u) | (unsigned)(124 - col0);
        unsigned kB0 = (fkey(yb.x) & 0xFFFFFF80u) | (unsigned)(127 - col0);
        unsigned kB1 = (fkey(yb.y) & 0xFFFFFF80u) | (unsigned)(126 - col0);
        unsigned kB2 = (fkey(yb.z) & 0xFFFFFF80u) | (unsigned)(125 - col0);
        unsigned kB3 = (fkey(yb.w) & 0xFFFFFF80u) | (unsigned)(124 - col0);

        KSWAP(kA0, kA1); KSWAP(kA2, kA3); KSWAP(kA0, kA2);
        KSWAP(kA1, kA3); KSWAP(kA1, kA2);
        KSWAP(kB0, kB1); KSWAP(kB2, kB3); KSWAP(kB0, kB2);
        KSWAP(kB1, kB3); KSWAP(kB1, kB2);

        unsigned keepA = 0u, keepB = 0u;
        #pragma unroll 8
        for (int i = 0; i < KSEL; ++i) {
            unsigned mA = __reduce_max_sync(0xffffffffu, kA0);
            unsigned mB = __reduce_max_sync(0xffffffffu, kB0);
            bool winA = (kA0 == mA);
            bool winB = (kB0 == mB);
            kA0 = winA ? kA1 : kA0;  kA1 = winA ? kA2 : kA1;
            kA2 = winA ? kA3 : kA2;  kA3 = winA ? 0u  : kA3;
            kB0 = winB ? kB1 : kB0;  kB1 = winB ? kB2 : kB1;
            kB2 = winB ? kB3 : kB2;  kB3 = winB ? 0u  : kB3;
            keepA = (lane == i) ? mA : keepA;
            keepB = (lane == i) ? mB : keepB;
        }

        // ---- adaptive gap check: tau >= 2(quant+split) error of the pair ----
        float ylA = unfkey(keepA & 0xFFFFFF80u);
        float y33A = unfkey(__reduce_max_sync(0xffffffffu, kA0) & 0xFFFFFF80u);
        float ynA = __shfl_down_sync(0xffffffffu, ylA, 1);
        if (lane == 31) ynA = y33A;
        float tauA = 1e-4f + 4.5e-5f * (fabsf(ylA) + fabsf(ynA));
        unsigned col_i_A = 127u - (keepA & 127u);
        float dA = ylA;
        if (__ballot_sync(0xffffffffu, (ylA - ynA) < tauA)) {
            float y0  = __shfl_sync(0xffffffffu, ylA, 0);
            float y31 = __shfl_sync(0xffffffffu, ylA, 31);
            float yt = y31 - (1e-4f + 9e-5f * fabsf(y0));
            fixup_row(x, vfp, rA, g_y + (size_t)rA * DIM, stA, candw, yt);
            uint2 p = stA[lane];
            col_i_A = p.x;
            dA = unfkey(p.y);
        }
        {
            float sg = 1.0f / (1.0f + __expf(-dA * inv_len));
            float xv = __ldg(&x[(size_t)rA * DIM + col_i_A]);
            out[(size_t)rA * KSEL + lane] = xv * sg;
        }

        if (hasB) {
            float ylB = unfkey(keepB & 0xFFFFFF80u);
            float y33B = unfkey(__reduce_max_sync(0xffffffffu, kB0) & 0xFFFFFF80u);
            float ynB = __shfl_down_sync(0xffffffffu, ylB, 1);
            if (lane == 31) ynB = y33B;
            float tauB = 1e-4f + 4.5e-5f * (fabsf(ylB) + fabsf(ynB));
            unsigned col_i_B = 127u - (keepB & 127u);
            float dB = ylB;
            if (__ballot_sync(0xffffffffu, (ylB - ynB) < tauB)) {
                float y0  = __shfl_sync(0xffffffffu, ylB, 0);
                float y31 = __shfl_sync(0xffffffffu, ylB, 31);
                float yt = y31 - (1e-4f + 9e-5f * fabsf(y0));
                fixup_row(x, vfp, rA + 1, g_y + (size_t)(rA + 1) * DIM, stB, candw, yt);
                uint2 p = stB[lane];
                col_i_B = p.x;
                dB = unfkey(p.y);
            }
            float sg = 1.0f / (1.0f + __expf(-dB * inv_len));
            float xv = __ldg(&x[(size_t)(rA + 1) * DIM + col_i_B]);
            out[(size_t)(rA + 1) * KSEL + lane] = xv * sg;
        }
        __syncwarp();
    }
}

// ---------------------------------------------------------------------------
extern "C" void kernel_launch(void* const* d_in, const int* in_sizes, int n_in,
                              void* d_out, int out_size) {
    const float* x = (const float*)d_in[0];
    const float* v = (const float*)d_in[1];
    float* out = (float*)d_out;
    const int nrows = in_sizes[0] / DIM;

    cudaFuncSetAttribute(gemm_kernel,
                         cudaFuncAttributeMaxDynamicSharedMemorySize, SMEM_A);

    prep_split<<<64, 256>>>(v);
    prep_finalize<<<1, 64>>>();
    const int grid_a = (nrows + ROWS_CTA - 1) / ROWS_CTA;
    gemm_kernel<<<grid_a, THREADS, SMEM_A>>>(x, nrows);
    const int grid_b = (nrows + 63) / 64;
    sel_kernel<<<grid_b, THREADS>>>(x, v, out, nrows);
}